// round 6
// baseline (speedup 1.0000x reference)
#include <cuda_runtime.h>
#include <cuda_bf16.h>
#include <cstdint>

#define NB 16
#define NT 2048
#define NV 512
#define BM 128
#define BN 128
#define BK 32   // bf16 elements per k-tile

// Scratch (allocation-free rule: __device__ globals).
__device__ __nv_bfloat16 g_A[(size_t)NB * NT * NV];   // L1, then reused as S
__device__ float g_KT[(size_t)NB * NV * NT];          // K transposed per batch
__device__ __nv_bfloat16 g_WqT[NV * NV];              // Wq^T in bf16, [n][k]
__device__ __nv_bfloat16 g_WvR[NV * NV];              // Wv in bf16, [n][k]
__device__ unsigned short g_pos[NB * NT];             // CSR positions (sorted)
__device__ int g_off[NB * (NV + 1)];                  // CSR offsets

__device__ __forceinline__ uint32_t smem_u32(const void* p) {
    return (uint32_t)__cvta_generic_to_shared(p);
}

// ---------------------------------------------------------------------------
// Wq transpose (512x512) -> bf16, [n][k] layout
// ---------------------------------------------------------------------------
__global__ void k_wqt(const float* __restrict__ W, __nv_bfloat16* __restrict__ WT) {
    __shared__ float t[32][33];
    int x = blockIdx.x * 32 + threadIdx.x;
    int y = blockIdx.y * 32 + threadIdx.y;
#pragma unroll
    for (int j = 0; j < 32; j += 8)
        t[threadIdx.y + j][threadIdx.x] = W[(size_t)(y + j) * NV + x];
    __syncthreads();
    x = blockIdx.y * 32 + threadIdx.x;
    y = blockIdx.x * 32 + threadIdx.y;
#pragma unroll
    for (int j = 0; j < 32; j += 8)
        WT[(size_t)(y + j) * NV + x] = __float2bfloat16(t[threadIdx.x][threadIdx.y + j]);
}

// ---------------------------------------------------------------------------
// Wv -> bf16 copy
// ---------------------------------------------------------------------------
__global__ void k_wv(const float* __restrict__ src, __nv_bfloat16* __restrict__ dst) {
    int i4 = (blockIdx.x * 256 + threadIdx.x) * 4;
    float4 v = *(const float4*)(src + i4);
    __nv_bfloat162* d2 = (__nv_bfloat162*)(dst + i4);
    d2[0] = __floats2bfloat162_rn(v.x, v.y);
    d2[1] = __floats2bfloat162_rn(v.z, v.w);
}

// ---------------------------------------------------------------------------
// CSR build: per batch, sorted position lists per vocab id.
// One block per batch, 512 threads (thread = vocab id v).
// ---------------------------------------------------------------------------
__global__ void k_csr(const int* __restrict__ idx,
                      unsigned short* __restrict__ pos,
                      int* __restrict__ off) {
    const int b = blockIdx.x, v = threadIdx.x;
    __shared__ int sidx[NT];
    __shared__ int wsum[16];
    for (int r = v; r < NT; r += 512) sidx[r] = idx[b * NT + r];
    __syncthreads();
    int c = 0;
    for (int r = 0; r < NT; r++) c += (sidx[r] == v);
    // block-wide exclusive scan of c
    const int lane = v & 31, w = v >> 5;
    int incl = c;
#pragma unroll
    for (int d = 1; d < 32; d <<= 1) {
        int x = __shfl_up_sync(0xffffffffu, incl, d);
        if (lane >= d) incl += x;
    }
    if (lane == 31) wsum[w] = incl;
    __syncthreads();
    if (w == 0) {
        int s = (lane < 16) ? wsum[lane] : 0;
#pragma unroll
        for (int d = 1; d < 16; d <<= 1) {
            int x = __shfl_up_sync(0xffffffffu, s, d);
            if (lane >= d) s += x;
        }
        if (lane < 16) wsum[lane] = s;  // inclusive warp sums
    }
    __syncthreads();
    const int excl = incl - c + (w ? wsum[w - 1] : 0);
    off[b * (NV + 1) + v] = excl;
    if (v == 511) off[b * (NV + 1) + NV] = NT;
    int o = excl;
    for (int r = 0; r < NT; r++)
        if (sidx[r] == v) pos[b * NT + (o++)] = (unsigned short)r;
}

// ---------------------------------------------------------------------------
// L1[b,s,v] = sum_{r<=s, idx[b,r]==v} pt[s-r], atomic-free via CSR.
// Block = (s-tile of 16, b); thread = v. Output bf16.
// ---------------------------------------------------------------------------
__global__ void k_build_l1(const unsigned short* __restrict__ pos,
                           const int* __restrict__ off,
                           const float* __restrict__ pt,
                           __nv_bfloat16* __restrict__ L1) {
    const int s0 = blockIdx.x * 16, b = blockIdx.y;
    const int v = threadIdx.x;
    const int smax = s0 + 15;
    __shared__ float ptsh[NT];
    for (int d = v; d <= smax; d += 512) ptsh[d] = pt[d];
    __syncthreads();
    float acc[16];
#pragma unroll
    for (int i = 0; i < 16; i++) acc[i] = 0.f;
    const int e0 = off[b * (NV + 1) + v], e1 = off[b * (NV + 1) + v + 1];
    const unsigned short* pb = pos + b * NT;
    for (int e = e0; e < e1; e++) {
        const int r = pb[e];
        if (r > smax) break;
        if (r <= s0) {
            const float* p = ptsh + (s0 - r);
#pragma unroll
            for (int i = 0; i < 16; i++) acc[i] += p[i];
        } else {
#pragma unroll
            for (int i = 0; i < 16; i++)
                if (s0 + i >= r) acc[i] += ptsh[s0 + i - r];
        }
    }
#pragma unroll
    for (int i = 0; i < 16; i++)
        L1[((size_t)(b * NT + s0 + i)) * NV + v] = __float2bfloat16(acc[i]);
}

// ---------------------------------------------------------------------------
// S[b,t,v] = sum_{s<=t, idx[b,s]==v} KT[b][idx[b,t]][s], atomic-free via CSR.
// Block = (t-tile of 8, b); thread = v. KT rows staged in shared (cp.async).
// ---------------------------------------------------------------------------
__global__ void k_scatter_s(const int* __restrict__ idx,
                            const unsigned short* __restrict__ pos,
                            const int* __restrict__ off,
                            const float* __restrict__ KT,
                            __nv_bfloat16* __restrict__ S) {
    extern __shared__ __align__(16) float rows[];  // [8][2064]
    __shared__ int qsh[8];
    const int t0 = blockIdx.x * 8, b = blockIdx.y;
    const int v = threadIdx.x;
    if (v < 8) qsh[v] = idx[b * NT + t0 + v];
    __syncthreads();
    const int tmax = t0 + 7;
    const int CH = (t0 + 11) >> 2;  // 16B chunks per staged row
    for (int id = v; id < 8 * CH; id += 512) {
        const int i = id / CH, c = id - i * CH;
        const float* src = KT + ((size_t)(b * NV + qsh[i])) * NT + c * 4;
        uint32_t dst = smem_u32(&rows[i * 2064 + c * 4]);
        asm volatile("cp.async.cg.shared.global [%0], [%1], 16;" ::"r"(dst), "l"(src));
    }
    asm volatile("cp.async.commit_group;");
    asm volatile("cp.async.wait_group 0;");
    __syncthreads();
    float acc[8];
#pragma unroll
    for (int i = 0; i < 8; i++) acc[i] = 0.f;
    const int e0 = off[b * (NV + 1) + v], e1 = off[b * (NV + 1) + v + 1];
    const unsigned short* pb = pos + b * NT;
    for (int e = e0; e < e1; e++) {
        const int s = pb[e];
        if (s > tmax) break;
        if (s <= t0) {
#pragma unroll
            for (int i = 0; i < 8; i++) acc[i] += rows[i * 2064 + s];
        } else {
#pragma unroll
            for (int i = 0; i < 8; i++)
                if (t0 + i >= s) acc[i] += rows[i * 2064 + s];
        }
    }
#pragma unroll
    for (int i = 0; i < 8; i++)
        S[((size_t)(b * NT + t0 + i)) * NV + v] = __float2bfloat16(acc[i]);
}

// ---------------------------------------------------------------------------
// bf16 GEMM, CTA 128x128, BK=32 (bf16), 8 warps of 64x32 each,
// cp.async double-buffered, stride-20-u32 padded smem (conflict-free frags).
// B row-major [n][k]. C[m,n] = sum_k A[m,k]*B[n,k], fp32 out.
//   TRANS_OUT=true : C[m,n] -> KT[b][n][s] via shared-staged transpose
// ---------------------------------------------------------------------------
template <bool TRANS_OUT>
__global__ void __launch_bounds__(256, 2)
gemm_bf16(const __nv_bfloat16* __restrict__ A,
          const __nv_bfloat16* __restrict__ Bsrc, float* __restrict__ C) {
    extern __shared__ __align__(16) uint32_t sm[];  // 10240 u32 = 40KB
    uint32_t* Asm = sm;          // [2][128][20] u32 (16 data + 4 pad per row)
    uint32_t* Bsm = sm + 5120;   // [2][128][20]

    const int tid = threadIdx.x;
    const int lane = tid & 31, warp = tid >> 5;
    const int wm = (warp & 1) * 64, wn = (warp >> 1) * 32;
    const int q = lane >> 2, t4 = lane & 3;
    const int m0 = blockIdx.y * BM, n0 = blockIdx.x * BN;

    float c[4][4][4];
#pragma unroll
    for (int i = 0; i < 4; i++)
#pragma unroll
        for (int j = 0; j < 4; j++)
#pragma unroll
            for (int r = 0; r < 4; r++) c[i][j][r] = 0.f;

#define ISSUE_TILE(KT_, BUF_)                                                  \
    do {                                                                       \
        _Pragma("unroll") for (int i_ = 0; i_ < 2; i_++) {                     \
            int f = tid + i_ * 256;                                            \
            int m_ = f >> 2, k4 = f & 3;                                       \
            const __nv_bfloat16* src =                                         \
                A + (size_t)(m0 + m_) * NV + (KT_) + k4 * 8;                   \
            uint32_t dst =                                                     \
                smem_u32(&Asm[(BUF_)*2560 + m_ * 20 + k4 * 4]);                \
            asm volatile("cp.async.cg.shared.global [%0], [%1], 16;" ::"r"(    \
                             dst),                                             \
                         "l"(src));                                            \
        }                                                                      \
        _Pragma("unroll") for (int i_ = 0; i_ < 2; i_++) {                     \
            int f = tid + i_ * 256;                                            \
            int n_ = f >> 2, k4 = f & 3;                                       \
            const __nv_bfloat16* src =                                         \
                Bsrc + (size_t)(n0 + n_) * NV + (KT_) + k4 * 8;                \
            uint32_t dst =                                                     \
                smem_u32(&Bsm[(BUF_)*2560 + n_ * 20 + k4 * 4]);                \
            asm volatile("cp.async.cg.shared.global [%0], [%1], 16;" ::"r"(    \
                             dst),                                             \
                         "l"(src));                                            \
        }                                                                      \
        asm volatile("cp.async.commit_group;");                                \
    } while (0)

    ISSUE_TILE(0, 0);
    const int NKT = NV / BK;  // 16
    for (int it = 0; it < NKT; it++) {
        const int buf = it & 1;
        if (it + 1 < NKT) {
            ISSUE_TILE((it + 1) * BK, buf ^ 1);
            asm volatile("cp.async.wait_group 1;");
        } else {
            asm volatile("cp.async.wait_group 0;");
        }
        __syncthreads();

        const uint32_t* Ab = Asm + buf * 2560;
        const uint32_t* Bb = Bsm + buf * 2560;
#pragma unroll
        for (int ks = 0; ks < 2; ks++) {
            const int c0 = ks * 8 + t4;
            const int c1 = c0 + 4;
            uint32_t a[4][4], bf_[4][2];
#pragma unroll
            for (int i = 0; i < 4; i++) {
                const int row = (wm + i * 16 + q) * 20;
                a[i][0] = Ab[row + c0];
                a[i][1] = Ab[row + 160 + c0];
                a[i][2] = Ab[row + c1];
                a[i][3] = Ab[row + 160 + c1];
            }
#pragma unroll
            for (int j = 0; j < 4; j++) {
                const int rn = (wn + j * 8 + q) * 20;
                bf_[j][0] = Bb[rn + c0];
                bf_[j][1] = Bb[rn + c1];
            }
#pragma unroll
            for (int i = 0; i < 4; i++)
#pragma unroll
                for (int j = 0; j < 4; j++)
                    asm volatile(
                        "mma.sync.aligned.m16n8k16.row.col.f32.bf16.bf16.f32 "
                        "{%0,%1,%2,%3}, {%4,%5,%6,%7}, {%8,%9}, {%0,%1,%2,%3};"
                        : "+f"(c[i][j][0]), "+f"(c[i][j][1]),
                          "+f"(c[i][j][2]), "+f"(c[i][j][3])
                        : "r"(a[i][0]), "r"(a[i][1]), "r"(a[i][2]),
                          "r"(a[i][3]), "r"(bf_[j][0]), "r"(bf_[j][1]));
        }
        __syncthreads();
    }
#undef ISSUE_TILE

    if (TRANS_OUT) {
        // C[m,n] -> KT[b][n][s], staged through shared for coalesced stores
        const int b = m0 >> 11;  // / NT
        const int s0 = m0 & (NT - 1);
        float* stg = (float*)sm;  // [64][136] floats = 34816B < 40960B
#pragma unroll
        for (int p = 0; p < 2; p++) {
            __syncthreads();
            if ((warp >> 2) == p) {
#pragma unroll
                for (int i = 0; i < 4; i++)
#pragma unroll
                    for (int j = 0; j < 4; j++)
#pragma unroll
                        for (int r = 0; r < 4; r++) {
                            int row = wm + i * 16 + q + (r >> 1) * 8;
                            int col = wn + j * 8 + 2 * t4 + (r & 1) - p * 64;
                            stg[col * 136 + row] = c[i][j][r];
                        }
            }
            __syncthreads();
            const int nn = tid >> 2, ch = tid & 3;
            float* dst = C + ((size_t)(b * NV + n0 + p * 64 + nn)) * NT + s0;
            const float* srow = stg + nn * 136;
#pragma unroll
            for (int w = 0; w < 8; w++) {
                int f = ch * 32 + w * 4;
                *(float4*)(dst + f) = *(const float4*)(srow + f);
            }
        }
    } else {
        float* Cb = C + (size_t)m0 * NV + n0;
#pragma unroll
        for (int i = 0; i < 4; i++)
#pragma unroll
            for (int j = 0; j < 4; j++) {
                const int row = wm + i * 16 + q;
                const int col = wn + j * 8 + 2 * t4;
                float2 v0 = make_float2(c[i][j][0], c[i][j][1]);
                float2 v1 = make_float2(c[i][j][2], c[i][j][3]);
                *(float2*)&Cb[(size_t)row * NV + col] = v0;
                *(float2*)&Cb[(size_t)(row + 8) * NV + col] = v1;
            }
    }
}

// ---------------------------------------------------------------------------
extern "C" void kernel_launch(void* const* d_in, const int* in_sizes, int n_in,
                              void* d_out, int out_size) {
    const int* idx = (const int*)d_in[0];     // (B,T) int32
    const float* pt = (const float*)d_in[1];  // (T,1) f32
    const float* Wq = (const float*)d_in[2];  // (V,V) f32
    const float* Wv = (const float*)d_in[3];  // (V,V) f32
    float* out = (float*)d_out;               // (B,T,V) f32

    __nv_bfloat16 *pA = nullptr, *pWqT = nullptr, *pWvR = nullptr;
    float* pKT = nullptr;
    unsigned short* pPos = nullptr;
    int* pOff = nullptr;
    cudaGetSymbolAddress((void**)&pA, g_A);
    cudaGetSymbolAddress((void**)&pKT, g_KT);
    cudaGetSymbolAddress((void**)&pWqT, g_WqT);
    cudaGetSymbolAddress((void**)&pWvR, g_WvR);
    cudaGetSymbolAddress((void**)&pPos, g_pos);
    cudaGetSymbolAddress((void**)&pOff, g_off);

    cudaFuncSetAttribute(gemm_bf16<true>,
                         cudaFuncAttributeMaxDynamicSharedMemorySize, 40960);
    cudaFuncSetAttribute(gemm_bf16<false>,
                         cudaFuncAttributeMaxDynamicSharedMemorySize, 40960);
    cudaFuncSetAttribute(k_scatter_s,
                         cudaFuncAttributeMaxDynamicSharedMemorySize, 66048);

    dim3 gridGemm(NV / BN, (NB * NT) / BM);  // (4, 256)

    // 0) weights to bf16 (WqT = Wq^T)
    k_wqt<<<dim3(16, 16), dim3(32, 8)>>>(Wq, pWqT);
    k_wv<<<(NV * NV) / 1024, 256>>>(Wv, pWvR);
    // 1) CSR of token positions per batch
    k_csr<<<NB, 512>>>(idx, pPos, pOff);
    // 2) L1 scatter (atomic-free), bf16 out
    k_build_l1<<<dim3(NT / 16, NB), 512>>>(pPos, pOff, pt, pA);
    // 3) K = L1 @ Wq -> KT[b][n][s] fp32
    gemm_bf16<true><<<gridGemm, 256, 40960>>>(pA, pWqT, pKT);
    // 4) S scatter (atomic-free), bf16 out (reuses g_A)
    k_scatter_s<<<dim3(NT / 8, NB), 512, 66048>>>(idx, pPos, pOff, pKT, pA);
    // 5) logits = S @ Wv^T, fp32 out
    gemm_bf16<false><<<gridGemm, 256, 40960>>>(pA, pWvR, out);
}

// round 7
// speedup vs baseline: 1.5187x; 1.5187x over previous
#include <cuda_runtime.h>
#include <cuda_bf16.h>
#include <cstdint>

#define NB 16
#define NT 2048
#define NV 512
#define BM 128
#define BN 128
#define BK 32    // bf16 elements per k-tile
#define NCH 16
#define CHW (NT / NCH)  // 128

// Scratch (allocation-free rule: __device__ globals).
__device__ __nv_bfloat16 g_A[(size_t)NB * NT * NV];   // L1, then reused as S
__device__ float g_KT[(size_t)NB * NV * NT];          // K transposed per batch
__device__ __nv_bfloat16 g_WqT[NV * NV];              // Wq^T in bf16, [n][k]
__device__ __nv_bfloat16 g_WvR[NV * NV];              // Wv in bf16, [n][k]
__device__ unsigned short g_pos[NB * NT];             // CSR positions (sorted)
__device__ int g_off[NB * (NV + 1)];                  // CSR offsets
__device__ int g_cnt[NB * NCH * NV];                  // per-chunk counts
__device__ int g_off2[NB * NCH * NV];                 // per-chunk start offsets

__device__ __forceinline__ uint32_t smem_u32(const void* p) {
    return (uint32_t)__cvta_generic_to_shared(p);
}

// ---------------------------------------------------------------------------
// Wq transpose (512x512) -> bf16, [n][k] layout
// ---------------------------------------------------------------------------
__global__ void k_wqt(const float* __restrict__ W, __nv_bfloat16* __restrict__ WT) {
    __shared__ float t[32][33];
    int x = blockIdx.x * 32 + threadIdx.x;
    int y = blockIdx.y * 32 + threadIdx.y;
#pragma unroll
    for (int j = 0; j < 32; j += 8)
        t[threadIdx.y + j][threadIdx.x] = W[(size_t)(y + j) * NV + x];
    __syncthreads();
    x = blockIdx.y * 32 + threadIdx.x;
    y = blockIdx.x * 32 + threadIdx.y;
#pragma unroll
    for (int j = 0; j < 32; j += 8)
        WT[(size_t)(y + j) * NV + x] = __float2bfloat16(t[threadIdx.x][threadIdx.y + j]);
}

// ---------------------------------------------------------------------------
// Wv -> bf16 copy
// ---------------------------------------------------------------------------
__global__ void k_wv(const float* __restrict__ src, __nv_bfloat16* __restrict__ dst) {
    int i4 = (blockIdx.x * 256 + threadIdx.x) * 4;
    float4 v = *(const float4*)(src + i4);
    __nv_bfloat162* d2 = (__nv_bfloat162*)(dst + i4);
    d2[0] = __floats2bfloat162_rn(v.x, v.y);
    d2[1] = __floats2bfloat162_rn(v.z, v.w);
}

// ---------------------------------------------------------------------------
// Parallel CSR build: hist (per 128-token chunk) -> scan -> fill
// ---------------------------------------------------------------------------
__global__ void k_hist(const int* __restrict__ idx, int* __restrict__ cnt) {
    const int c = blockIdx.x, b = blockIdx.y, v = threadIdx.x;
    __shared__ int sidx[CHW];
    if (v < CHW) sidx[v] = idx[b * NT + c * CHW + v];
    __syncthreads();
    int n = 0;
#pragma unroll 8
    for (int r = 0; r < CHW; r++) n += (sidx[r] == v);
    cnt[(b * NCH + c) * NV + v] = n;
}

__global__ void k_scan(const int* __restrict__ cnt, int* __restrict__ off,
                       int* __restrict__ off2) {
    const int b = blockIdx.x, v = threadIdx.x;
    __shared__ int wsum[16];
    int c[NCH];
    int tot = 0;
#pragma unroll
    for (int j = 0; j < NCH; j++) {
        c[j] = cnt[(b * NCH + j) * NV + v];
        tot += c[j];
    }
    // block-wide exclusive scan of tot over v
    const int lane = v & 31, w = v >> 5;
    int incl = tot;
#pragma unroll
    for (int d = 1; d < 32; d <<= 1) {
        int x = __shfl_up_sync(0xffffffffu, incl, d);
        if (lane >= d) incl += x;
    }
    if (lane == 31) wsum[w] = incl;
    __syncthreads();
    if (w == 0) {
        int s = (lane < 16) ? wsum[lane] : 0;
#pragma unroll
        for (int d = 1; d < 16; d <<= 1) {
            int x = __shfl_up_sync(0xffffffffu, s, d);
            if (lane >= d) s += x;
        }
        if (lane < 16) wsum[lane] = s;
    }
    __syncthreads();
    int o = incl - tot + (w ? wsum[w - 1] : 0);  // exclusive prefix
    off[b * (NV + 1) + v] = o;
    if (v == NV - 1) off[b * (NV + 1) + NV] = NT;
#pragma unroll
    for (int j = 0; j < NCH; j++) {
        off2[(b * NCH + j) * NV + v] = o;
        o += c[j];
    }
}

__global__ void k_fill(const int* __restrict__ idx, const int* __restrict__ off2,
                       unsigned short* __restrict__ pos) {
    const int c = blockIdx.x, b = blockIdx.y, v = threadIdx.x;
    __shared__ int sidx[CHW];
    if (v < CHW) sidx[v] = idx[b * NT + c * CHW + v];
    __syncthreads();
    int o = off2[(b * NCH + c) * NV + v];
    for (int r = 0; r < CHW; r++)
        if (sidx[r] == v) pos[b * NT + (o++)] = (unsigned short)(c * CHW + r);
}

// ---------------------------------------------------------------------------
// L1[b,s,v] = sum_{r<=s, idx[b,r]==v} pt[s-r], atomic-free via CSR.
// Block = (s-tile of 32, b); thread = v. Positions staged in shared. bf16 out.
// ---------------------------------------------------------------------------
__global__ void __launch_bounds__(512)
k_build_l1(const unsigned short* __restrict__ pos, const int* __restrict__ off,
           const float* __restrict__ pt, __nv_bfloat16* __restrict__ L1) {
    const int s0 = blockIdx.x * 32, b = blockIdx.y;
    const int v = threadIdx.x;
    const int smax = s0 + 31;
    __shared__ float ptsh[NT];
    __shared__ unsigned short psh[NT];
    for (int d = v; d <= smax; d += 512) ptsh[d] = pt[d];
    for (int d = v; d < NT; d += 512) psh[d] = pos[b * NT + d];
    __syncthreads();
    float acc[32];
#pragma unroll
    for (int i = 0; i < 32; i++) acc[i] = 0.f;
    const int e0 = off[b * (NV + 1) + v], e1 = off[b * (NV + 1) + v + 1];
    for (int e = e0; e < e1; e++) {
        const int r = psh[e];
        if (r > smax) break;
        if (r <= s0) {
            const float* p = ptsh + (s0 - r);
#pragma unroll
            for (int i = 0; i < 32; i++) acc[i] += p[i];
        } else {
#pragma unroll
            for (int i = 0; i < 32; i++)
                if (s0 + i >= r) acc[i] += ptsh[s0 + i - r];
        }
    }
#pragma unroll
    for (int i = 0; i < 32; i++)
        L1[((size_t)(b * NT + s0 + i)) * NV + v] = __float2bfloat16(acc[i]);
}

// ---------------------------------------------------------------------------
// S[b,t,v] = sum_{s<=t, idx[b,s]==v} KT[b][idx[b,t]][s]  (shared atomics,
// measured-good in R5). bf16 out.
// ---------------------------------------------------------------------------
__global__ void k_scatter_s(const int* __restrict__ idx,
                            const float* __restrict__ KT,
                            __nv_bfloat16* __restrict__ S) {
    const int t = blockIdx.x, b = blockIdx.y;
    __shared__ float acc[NV];
    for (int v = threadIdx.x; v < NV; v += blockDim.x) acc[v] = 0.f;
    __syncthreads();
    const int* ib = idx + (size_t)b * NT;
    const int q = ib[t];
    const float* krow = KT + ((size_t)b * NV + q) * NT;
    for (int s = threadIdx.x; s <= t; s += blockDim.x)
        atomicAdd(&acc[ib[s]], krow[s]);
    __syncthreads();
    __nv_bfloat16* out = S + ((size_t)(b * NT + t)) * NV;
    for (int v = threadIdx.x; v < NV; v += blockDim.x)
        out[v] = __float2bfloat16(acc[v]);
}

// ---------------------------------------------------------------------------
// bf16 GEMM, CTA 128x128, BK=32 (bf16), 8 warps of 64x32 each,
// cp.async double-buffered, stride-20-u32 padded smem (conflict-free frags).
// B row-major [n][k]. C[m,n] = sum_k A[m,k]*B[n,k], fp32 out.
//   TRANS_OUT=true : C[m,n] -> KT[b][n][s] via shared-staged transpose
// ---------------------------------------------------------------------------
template <bool TRANS_OUT>
__global__ void __launch_bounds__(256, 2)
gemm_bf16(const __nv_bfloat16* __restrict__ A,
          const __nv_bfloat16* __restrict__ Bsrc, float* __restrict__ C) {
    extern __shared__ __align__(16) uint32_t sm[];  // 10240 u32 = 40KB
    uint32_t* Asm = sm;          // [2][128][20] u32 (16 data + 4 pad per row)
    uint32_t* Bsm = sm + 5120;   // [2][128][20]

    const int tid = threadIdx.x;
    const int lane = tid & 31, warp = tid >> 5;
    const int wm = (warp & 1) * 64, wn = (warp >> 1) * 32;
    const int q = lane >> 2, t4 = lane & 3;
    const int m0 = blockIdx.y * BM, n0 = blockIdx.x * BN;

    float c[4][4][4];
#pragma unroll
    for (int i = 0; i < 4; i++)
#pragma unroll
        for (int j = 0; j < 4; j++)
#pragma unroll
            for (int r = 0; r < 4; r++) c[i][j][r] = 0.f;

#define ISSUE_TILE(KT_, BUF_)                                                  \
    do {                                                                       \
        _Pragma("unroll") for (int i_ = 0; i_ < 2; i_++) {                     \
            int f = tid + i_ * 256;                                            \
            int m_ = f >> 2, k4 = f & 3;                                       \
            const __nv_bfloat16* src =                                         \
                A + (size_t)(m0 + m_) * NV + (KT_) + k4 * 8;                   \
            uint32_t dst =                                                     \
                smem_u32(&Asm[(BUF_)*2560 + m_ * 20 + k4 * 4]);                \
            asm volatile("cp.async.cg.shared.global [%0], [%1], 16;" ::"r"(    \
                             dst),                                             \
                         "l"(src));                                            \
        }                                                                      \
        _Pragma("unroll") for (int i_ = 0; i_ < 2; i_++) {                     \
            int f = tid + i_ * 256;                                            \
            int n_ = f >> 2, k4 = f & 3;                                       \
            const __nv_bfloat16* src =                                         \
                Bsrc + (size_t)(n0 + n_) * NV + (KT_) + k4 * 8;                \
            uint32_t dst =                                                     \
                smem_u32(&Bsm[(BUF_)*2560 + n_ * 20 + k4 * 4]);                \
            asm volatile("cp.async.cg.shared.global [%0], [%1], 16;" ::"r"(    \
                             dst),                                             \
                         "l"(src));                                            \
        }                                                                      \
        asm volatile("cp.async.commit_group;");                                \
    } while (0)

    ISSUE_TILE(0, 0);
    const int NKT = NV / BK;  // 16
    for (int it = 0; it < NKT; it++) {
        const int buf = it & 1;
        if (it + 1 < NKT) {
            ISSUE_TILE((it + 1) * BK, buf ^ 1);
            asm volatile("cp.async.wait_group 1;");
        } else {
            asm volatile("cp.async.wait_group 0;");
        }
        __syncthreads();

        const uint32_t* Ab = Asm + buf * 2560;
        const uint32_t* Bb = Bsm + buf * 2560;
#pragma unroll
        for (int ks = 0; ks < 2; ks++) {
            const int c0 = ks * 8 + t4;
            const int c1 = c0 + 4;
            uint32_t a[4][4], bf_[4][2];
#pragma unroll
            for (int i = 0; i < 4; i++) {
                const int row = (wm + i * 16 + q) * 20;
                a[i][0] = Ab[row + c0];
                a[i][1] = Ab[row + 160 + c0];
                a[i][2] = Ab[row + c1];
                a[i][3] = Ab[row + 160 + c1];
            }
#pragma unroll
            for (int j = 0; j < 4; j++) {
                const int rn = (wn + j * 8 + q) * 20;
                bf_[j][0] = Bb[rn + c0];
                bf_[j][1] = Bb[rn + c1];
            }
#pragma unroll
            for (int i = 0; i < 4; i++)
#pragma unroll
                for (int j = 0; j < 4; j++)
                    asm volatile(
                        "mma.sync.aligned.m16n8k16.row.col.f32.bf16.bf16.f32 "
                        "{%0,%1,%2,%3}, {%4,%5,%6,%7}, {%8,%9}, {%0,%1,%2,%3};"
                        : "+f"(c[i][j][0]), "+f"(c[i][j][1]),
                          "+f"(c[i][j][2]), "+f"(c[i][j][3])
                        : "r"(a[i][0]), "r"(a[i][1]), "r"(a[i][2]),
                          "r"(a[i][3]), "r"(bf_[j][0]), "r"(bf_[j][1]));
        }
        __syncthreads();
    }
#undef ISSUE_TILE

    if (TRANS_OUT) {
        // C[m,n] -> KT[b][n][s], staged through shared for coalesced stores
        const int b = m0 >> 11;  // / NT
        const int s0 = m0 & (NT - 1);
        float* stg = (float*)sm;  // [64][136] floats = 34816B < 40960B
#pragma unroll
        for (int p = 0; p < 2; p++) {
            __syncthreads();
            if ((warp >> 2) == p) {
#pragma unroll
                for (int i = 0; i < 4; i++)
#pragma unroll
                    for (int j = 0; j < 4; j++)
#pragma unroll
                        for (int r = 0; r < 4; r++) {
                            int row = wm + i * 16 + q + (r >> 1) * 8;
                            int col = wn + j * 8 + 2 * t4 + (r & 1) - p * 64;
                            stg[col * 136 + row] = c[i][j][r];
                        }
            }
            __syncthreads();
            const int nn = tid >> 2, ch = tid & 3;
            float* dst = C + ((size_t)(b * NV + n0 + p * 64 + nn)) * NT + s0;
            const float* srow = stg + nn * 136;
#pragma unroll
            for (int w = 0; w < 8; w++) {
                int f = ch * 32 + w * 4;
                *(float4*)(dst + f) = *(const float4*)(srow + f);
            }
        }
    } else {
        float* Cb = C + (size_t)m0 * NV + n0;
#pragma unroll
        for (int i = 0; i < 4; i++)
#pragma unroll
            for (int j = 0; j < 4; j++) {
                const int row = wm + i * 16 + q;
                const int col = wn + j * 8 + 2 * t4;
                float2 v0 = make_float2(c[i][j][0], c[i][j][1]);
                float2 v1 = make_float2(c[i][j][2], c[i][j][3]);
                *(float2*)&Cb[(size_t)row * NV + col] = v0;
                *(float2*)&Cb[(size_t)(row + 8) * NV + col] = v1;
            }
    }
}

// ---------------------------------------------------------------------------
extern "C" void kernel_launch(void* const* d_in, const int* in_sizes, int n_in,
                              void* d_out, int out_size) {
    const int* idx = (const int*)d_in[0];     // (B,T) int32
    const float* pt = (const float*)d_in[1];  // (T,1) f32
    const float* Wq = (const float*)d_in[2];  // (V,V) f32
    const float* Wv = (const float*)d_in[3];  // (V,V) f32
    float* out = (float*)d_out;               // (B,T,V) f32

    __nv_bfloat16 *pA = nullptr, *pWqT = nullptr, *pWvR = nullptr;
    float* pKT = nullptr;
    unsigned short* pPos = nullptr;
    int *pOff = nullptr, *pCnt = nullptr, *pOff2 = nullptr;
    cudaGetSymbolAddress((void**)&pA, g_A);
    cudaGetSymbolAddress((void**)&pKT, g_KT);
    cudaGetSymbolAddress((void**)&pWqT, g_WqT);
    cudaGetSymbolAddress((void**)&pWvR, g_WvR);
    cudaGetSymbolAddress((void**)&pPos, g_pos);
    cudaGetSymbolAddress((void**)&pOff, g_off);
    cudaGetSymbolAddress((void**)&pCnt, g_cnt);
    cudaGetSymbolAddress((void**)&pOff2, g_off2);

    cudaFuncSetAttribute(gemm_bf16<true>,
                         cudaFuncAttributeMaxDynamicSharedMemorySize, 40960);
    cudaFuncSetAttribute(gemm_bf16<false>,
                         cudaFuncAttributeMaxDynamicSharedMemorySize, 40960);

    dim3 gridGemm(NV / BN, (NB * NT) / BM);  // (4, 256)

    // 0) weights to bf16 (WqT = Wq^T)
    k_wqt<<<dim3(16, 16), dim3(32, 8)>>>(Wq, pWqT);
    k_wv<<<(NV * NV) / 1024, 256>>>(Wv, pWvR);
    // 1) CSR of token positions per batch (parallel: hist -> scan -> fill)
    k_hist<<<dim3(NCH, NB), 512>>>(idx, pCnt);
    k_scan<<<NB, 512>>>(pCnt, pOff, pOff2);
    k_fill<<<dim3(NCH, NB), 512>>>(idx, pOff2, pPos);
    // 2) L1 scatter (atomic-free via CSR), bf16 out
    k_build_l1<<<dim3(NT / 32, NB), 512>>>(pPos, pOff, pt, pA);
    // 3) K = L1 @ Wq -> KT[b][n][s] fp32
    gemm_bf16<true><<<gridGemm, 256, 40960>>>(pA, pWqT, pKT);
    // 4) S scatter (shared atomics), bf16 out (reuses g_A)
    k_scatter_s<<<dim3(NT, NB), 256>>>(idx, pKT, pA);
    // 5) logits = S @ Wv^T, fp32 out
    gemm_bf16<false><<<gridGemm, 256, 40960>>>(pA, pWvR, out);
}

// round 8
// speedup vs baseline: 1.7506x; 1.1527x over previous
#include <cuda_runtime.h>
#include <cuda_bf16.h>
#include <cstdint>

#define NB 16
#define NT 2048
#define NV 512
#define BM 128
#define BN 128
#define BK 32    // bf16 elements per k-tile
#define NCH 16
#define CHW (NT / NCH)  // 128

// Scratch (allocation-free rule: __device__ globals).
__device__ __nv_bfloat16 g_A[(size_t)NB * NT * NV];   // L1, then reused as S
__device__ float g_KT[(size_t)NB * NV * NT];          // K transposed per batch
__device__ __nv_bfloat16 g_WqT[NV * NV];              // Wq^T in bf16, [n][k]
__device__ __nv_bfloat16 g_WvR[NV * NV];              // Wv in bf16, [n][k]
__device__ unsigned short g_pos[NB * NT];             // CSR positions (sorted)
__device__ int g_off[NB * (NV + 1)];                  // CSR offsets
__device__ int g_cnt[NB * NCH * NV];                  // per-chunk counts
__device__ int g_off2[NB * NCH * NV];                 // per-chunk start offsets

__device__ __forceinline__ uint32_t smem_u32(const void* p) {
    return (uint32_t)__cvta_generic_to_shared(p);
}

// ---------------------------------------------------------------------------
// Wq transpose (512x512) -> bf16, [n][k] layout
// ---------------------------------------------------------------------------
__global__ void k_wqt(const float* __restrict__ W, __nv_bfloat16* __restrict__ WT) {
    __shared__ float t[32][33];
    int x = blockIdx.x * 32 + threadIdx.x;
    int y = blockIdx.y * 32 + threadIdx.y;
#pragma unroll
    for (int j = 0; j < 32; j += 8)
        t[threadIdx.y + j][threadIdx.x] = W[(size_t)(y + j) * NV + x];
    __syncthreads();
    x = blockIdx.y * 32 + threadIdx.x;
    y = blockIdx.x * 32 + threadIdx.y;
#pragma unroll
    for (int j = 0; j < 32; j += 8)
        WT[(size_t)(y + j) * NV + x] = __float2bfloat16(t[threadIdx.x][threadIdx.y + j]);
}

// ---------------------------------------------------------------------------
// Wv -> bf16 copy
// ---------------------------------------------------------------------------
__global__ void k_wv(const float* __restrict__ src, __nv_bfloat16* __restrict__ dst) {
    int i4 = (blockIdx.x * 256 + threadIdx.x) * 4;
    float4 v = *(const float4*)(src + i4);
    __nv_bfloat162* d2 = (__nv_bfloat162*)(dst + i4);
    d2[0] = __floats2bfloat162_rn(v.x, v.y);
    d2[1] = __floats2bfloat162_rn(v.z, v.w);
}

// ---------------------------------------------------------------------------
// Parallel CSR build: hist (per 128-token chunk) -> scan -> fill
// ---------------------------------------------------------------------------
__global__ void k_hist(const int* __restrict__ idx, int* __restrict__ cnt) {
    const int c = blockIdx.x, b = blockIdx.y, v = threadIdx.x;
    __shared__ int sidx[CHW];
    if (v < CHW) sidx[v] = idx[b * NT + c * CHW + v];
    __syncthreads();
    int n = 0;
#pragma unroll 8
    for (int r = 0; r < CHW; r++) n += (sidx[r] == v);
    cnt[(b * NCH + c) * NV + v] = n;
}

__global__ void k_scan(const int* __restrict__ cnt, int* __restrict__ off,
                       int* __restrict__ off2) {
    const int b = blockIdx.x, v = threadIdx.x;
    __shared__ int wsum[16];
    int c[NCH];
    int tot = 0;
#pragma unroll
    for (int j = 0; j < NCH; j++) {
        c[j] = cnt[(b * NCH + j) * NV + v];
        tot += c[j];
    }
    const int lane = v & 31, w = v >> 5;
    int incl = tot;
#pragma unroll
    for (int d = 1; d < 32; d <<= 1) {
        int x = __shfl_up_sync(0xffffffffu, incl, d);
        if (lane >= d) incl += x;
    }
    if (lane == 31) wsum[w] = incl;
    __syncthreads();
    if (w == 0) {
        int s = (lane < 16) ? wsum[lane] : 0;
#pragma unroll
        for (int d = 1; d < 16; d <<= 1) {
            int x = __shfl_up_sync(0xffffffffu, s, d);
            if (lane >= d) s += x;
        }
        if (lane < 16) wsum[lane] = s;
    }
    __syncthreads();
    int o = incl - tot + (w ? wsum[w - 1] : 0);  // exclusive prefix
    off[b * (NV + 1) + v] = o;
    if (v == NV - 1) off[b * (NV + 1) + NV] = NT;
#pragma unroll
    for (int j = 0; j < NCH; j++) {
        off2[(b * NCH + j) * NV + v] = o;
        o += c[j];
    }
}

__global__ void k_fill(const int* __restrict__ idx, const int* __restrict__ off2,
                       unsigned short* __restrict__ pos) {
    const int c = blockIdx.x, b = blockIdx.y, v = threadIdx.x;
    __shared__ int sidx[CHW];
    if (v < CHW) sidx[v] = idx[b * NT + c * CHW + v];
    __syncthreads();
    int o = off2[(b * NCH + c) * NV + v];
    for (int r = 0; r < CHW; r++)
        if (sidx[r] == v) pos[b * NT + (o++)] = (unsigned short)(c * CHW + r);
}

// ---------------------------------------------------------------------------
// L1[b,s,v] = sum_{r<=s, idx[b,r]==v} pt[s-r], atomic-free via CSR.
// Block = (s-tile of 32, b); thread = v. Positions staged in shared. bf16 out.
// ---------------------------------------------------------------------------
__global__ void __launch_bounds__(512)
k_build_l1(const unsigned short* __restrict__ pos, const int* __restrict__ off,
           const float* __restrict__ pt, __nv_bfloat16* __restrict__ L1) {
    const int s0 = blockIdx.x * 32, b = blockIdx.y;
    const int v = threadIdx.x;
    const int smax = s0 + 31;
    __shared__ float ptsh[NT];
    __shared__ unsigned short psh[NT];
    for (int d = v; d <= smax; d += 512) ptsh[d] = pt[d];
    for (int d = v; d < NT; d += 512) psh[d] = pos[b * NT + d];
    __syncthreads();
    float acc[32];
#pragma unroll
    for (int i = 0; i < 32; i++) acc[i] = 0.f;
    const int e0 = off[b * (NV + 1) + v], e1 = off[b * (NV + 1) + v + 1];
    for (int e = e0; e < e1; e++) {
        const int r = psh[e];
        if (r > smax) break;
        if (r <= s0) {
            const float* p = ptsh + (s0 - r);
#pragma unroll
            for (int i = 0; i < 32; i++) acc[i] += p[i];
        } else {
#pragma unroll
            for (int i = 0; i < 32; i++)
                if (s0 + i >= r) acc[i] += ptsh[s0 + i - r];
        }
    }
#pragma unroll
    for (int i = 0; i < 32; i++)
        L1[((size_t)(b * NT + s0 + i)) * NV + v] = __float2bfloat16(acc[i]);
}

// ---------------------------------------------------------------------------
// S-scatter, grouped by query token q (atomic-free, single pass per (b,q)):
//   For block (q, b): Tq = {t : idx_t = q} (from CSR, sorted).
//   Thread v walks its own CSR s-list once, acc += col[s], and snapshots
//   S[t,v] at each t in Tq.   col = KT[b][q][:] staged in shared.
// ---------------------------------------------------------------------------
__global__ void __launch_bounds__(512)
k_scatter_q(const unsigned short* __restrict__ pos, const int* __restrict__ off,
            const float* __restrict__ KT, __nv_bfloat16* __restrict__ S) {
    const int q = blockIdx.x, b = blockIdx.y;
    const int v = threadIdx.x;
    __shared__ float colsh[NT];
    __shared__ unsigned short psh[NT];
    __shared__ int tq0sh[2];

    if (v < 2) tq0sh[v] = off[b * (NV + 1) + q + v];
    __syncthreads();
    const int eq0 = tq0sh[0], eq1 = tq0sh[1];
    const int lenT = eq1 - eq0;
    if (lenT == 0) return;  // no t maps to this q

    const unsigned short* pb = pos + b * NT;
    const int tlast = pb[eq1 - 1];

    // stage K column (KT row, contiguous) up to tlast via cp.async
    {
        const float* src = KT + ((size_t)(b * NV + q)) * NT;
        for (int c4 = v; c4 * 4 <= tlast; c4 += 512) {
            uint32_t dst = smem_u32(&colsh[c4 * 4]);
            asm volatile("cp.async.cg.shared.global [%0], [%1], 16;" ::"r"(dst),
                         "l"(src + c4 * 4));
        }
        asm volatile("cp.async.commit_group;");
    }
    // stage full position list for this batch (only entries <= tlast needed,
    // but staging all 2048 shorts = 4KB is trivial and branch-free)
    for (int d = v; d < NT; d += 512) psh[d] = pb[d];
    asm volatile("cp.async.wait_group 0;");
    __syncthreads();

    // walk own s-list once, snapshotting at each t in Tq
    int e = off[b * (NV + 1) + v];
    const int e1 = off[b * (NV + 1) + v + 1];
    float acc = 0.f;
    __nv_bfloat16* Sb = S + (size_t)b * NT * NV + v;
    for (int j = 0; j < lenT; j++) {
        const int t = psh[eq0 + j];
        while (e < e1 && psh[e] <= t) { acc += colsh[psh[e]]; e++; }
        Sb[(size_t)t * NV] = __float2bfloat16(acc);
    }
}

// ---------------------------------------------------------------------------
// bf16 GEMM, CTA 128x128, BK=32 (bf16), 8 warps of 64x32 each,
// cp.async double-buffered, stride-20-u32 padded smem (conflict-free frags).
// B row-major [n][k]. C[m,n] = sum_k A[m,k]*B[n,k], fp32 out.
//   TRANS_OUT=true : C[m,n] -> KT[b][n][s] via shared-staged transpose
// ---------------------------------------------------------------------------
template <bool TRANS_OUT>
__global__ void __launch_bounds__(256, 2)
gemm_bf16(const __nv_bfloat16* __restrict__ A,
          const __nv_bfloat16* __restrict__ Bsrc, float* __restrict__ C) {
    extern __shared__ __align__(16) uint32_t sm[];  // 10240 u32 = 40KB
    uint32_t* Asm = sm;          // [2][128][20] u32 (16 data + 4 pad per row)
    uint32_t* Bsm = sm + 5120;   // [2][128][20]

    const int tid = threadIdx.x;
    const int lane = tid & 31, warp = tid >> 5;
    const int wm = (warp & 1) * 64, wn = (warp >> 1) * 32;
    const int q = lane >> 2, t4 = lane & 3;
    const int m0 = blockIdx.y * BM, n0 = blockIdx.x * BN;

    float c[4][4][4];
#pragma unroll
    for (int i = 0; i < 4; i++)
#pragma unroll
        for (int j = 0; j < 4; j++)
#pragma unroll
            for (int r = 0; r < 4; r++) c[i][j][r] = 0.f;

#define ISSUE_TILE(KT_, BUF_)                                                  \
    do {                                                                       \
        _Pragma("unroll") for (int i_ = 0; i_ < 2; i_++) {                     \
            int f = tid + i_ * 256;                                            \
            int m_ = f >> 2, k4 = f & 3;                                       \
            const __nv_bfloat16* src =                                         \
                A + (size_t)(m0 + m_) * NV + (KT_) + k4 * 8;                   \
            uint32_t dst =                                                     \
                smem_u32(&Asm[(BUF_)*2560 + m_ * 20 + k4 * 4]);                \
            asm volatile("cp.async.cg.shared.global [%0], [%1], 16;" ::"r"(    \
                             dst),                                             \
                         "l"(src));                                            \
        }                                                                      \
        _Pragma("unroll") for (int i_ = 0; i_ < 2; i_++) {                     \
            int f = tid + i_ * 256;                                            \
            int n_ = f >> 2, k4 = f & 3;                                       \
            const __nv_bfloat16* src =                                         \
                Bsrc + (size_t)(n0 + n_) * NV + (KT_) + k4 * 8;                \
            uint32_t dst =                                                     \
                smem_u32(&Bsm[(BUF_)*2560 + n_ * 20 + k4 * 4]);                \
            asm volatile("cp.async.cg.shared.global [%0], [%1], 16;" ::"r"(    \
                             dst),                                             \
                         "l"(src));                                            \
        }                                                                      \
        asm volatile("cp.async.commit_group;");                                \
    } while (0)

    ISSUE_TILE(0, 0);
    const int NKT = NV / BK;  // 16
    for (int it = 0; it < NKT; it++) {
        const int buf = it & 1;
        if (it + 1 < NKT) {
            ISSUE_TILE((it + 1) * BK, buf ^ 1);
            asm volatile("cp.async.wait_group 1;");
        } else {
            asm volatile("cp.async.wait_group 0;");
        }
        __syncthreads();

        const uint32_t* Ab = Asm + buf * 2560;
        const uint32_t* Bb = Bsm + buf * 2560;
#pragma unroll
        for (int ks = 0; ks < 2; ks++) {
            const int c0 = ks * 8 + t4;
            const int c1 = c0 + 4;
            uint32_t a[4][4], bf_[4][2];
#pragma unroll
            for (int i = 0; i < 4; i++) {
                const int row = (wm + i * 16 + q) * 20;
                a[i][0] = Ab[row + c0];
                a[i][1] = Ab[row + 160 + c0];
                a[i][2] = Ab[row + c1];
                a[i][3] = Ab[row + 160 + c1];
            }
#pragma unroll
            for (int j = 0; j < 4; j++) {
                const int rn = (wn + j * 8 + q) * 20;
                bf_[j][0] = Bb[rn + c0];
                bf_[j][1] = Bb[rn + c1];
            }
#pragma unroll
            for (int i = 0; i < 4; i++)
#pragma unroll
                for (int j = 0; j < 4; j++)
                    asm volatile(
                        "mma.sync.aligned.m16n8k16.row.col.f32.bf16.bf16.f32 "
                        "{%0,%1,%2,%3}, {%4,%5,%6,%7}, {%8,%9}, {%0,%1,%2,%3};"
                        : "+f"(c[i][j][0]), "+f"(c[i][j][1]),
                          "+f"(c[i][j][2]), "+f"(c[i][j][3])
                        : "r"(a[i][0]), "r"(a[i][1]), "r"(a[i][2]),
                          "r"(a[i][3]), "r"(bf_[j][0]), "r"(bf_[j][1]));
        }
        __syncthreads();
    }
#undef ISSUE_TILE

    if (TRANS_OUT) {
        // C[m,n] -> KT[b][n][s], staged through shared for coalesced stores
        const int b = m0 >> 11;  // / NT
        const int s0 = m0 & (NT - 1);
        float* stg = (float*)sm;  // [64][136] floats = 34816B < 40960B
#pragma unroll
        for (int p = 0; p < 2; p++) {
            __syncthreads();
            if ((warp >> 2) == p) {
#pragma unroll
                for (int i = 0; i < 4; i++)
#pragma unroll
                    for (int j = 0; j < 4; j++)
#pragma unroll
                        for (int r = 0; r < 4; r++) {
                            int row = wm + i * 16 + q + (r >> 1) * 8;
                            int col = wn + j * 8 + 2 * t4 + (r & 1) - p * 64;
                            stg[col * 136 + row] = c[i][j][r];
                        }
            }
            __syncthreads();
            const int nn = tid >> 2, ch = tid & 3;
            float* dst = C + ((size_t)(b * NV + n0 + p * 64 + nn)) * NT + s0;
            const float* srow = stg + nn * 136;
#pragma unroll
            for (int w = 0; w < 8; w++) {
                int f = ch * 32 + w * 4;
                *(float4*)(dst + f) = *(const float4*)(srow + f);
            }
        }
    } else {
        float* Cb = C + (size_t)m0 * NV + n0;
#pragma unroll
        for (int i = 0; i < 4; i++)
#pragma unroll
            for (int j = 0; j < 4; j++) {
                const int row = wm + i * 16 + q;
                const int col = wn + j * 8 + 2 * t4;
                float2 v0 = make_float2(c[i][j][0], c[i][j][1]);
                float2 v1 = make_float2(c[i][j][2], c[i][j][3]);
                *(float2*)&Cb[(size_t)row * NV + col] = v0;
                *(float2*)&Cb[(size_t)(row + 8) * NV + col] = v1;
            }
    }
}

// ---------------------------------------------------------------------------
extern "C" void kernel_launch(void* const* d_in, const int* in_sizes, int n_in,
                              void* d_out, int out_size) {
    const int* idx = (const int*)d_in[0];     // (B,T) int32
    const float* pt = (const float*)d_in[1];  // (T,1) f32
    const float* Wq = (const float*)d_in[2];  // (V,V) f32
    const float* Wv = (const float*)d_in[3];  // (V,V) f32
    float* out = (float*)d_out;               // (B,T,V) f32

    __nv_bfloat16 *pA = nullptr, *pWqT = nullptr, *pWvR = nullptr;
    float* pKT = nullptr;
    unsigned short* pPos = nullptr;
    int *pOff = nullptr, *pCnt = nullptr, *pOff2 = nullptr;
    cudaGetSymbolAddress((void**)&pA, g_A);
    cudaGetSymbolAddress((void**)&pKT, g_KT);
    cudaGetSymbolAddress((void**)&pWqT, g_WqT);
    cudaGetSymbolAddress((void**)&pWvR, g_WvR);
    cudaGetSymbolAddress((void**)&pPos, g_pos);
    cudaGetSymbolAddress((void**)&pOff, g_off);
    cudaGetSymbolAddress((void**)&pCnt, g_cnt);
    cudaGetSymbolAddress((void**)&pOff2, g_off2);

    cudaFuncSetAttribute(gemm_bf16<true>,
                         cudaFuncAttributeMaxDynamicSharedMemorySize, 40960);
    cudaFuncSetAttribute(gemm_bf16<false>,
                         cudaFuncAttributeMaxDynamicSharedMemorySize, 40960);

    dim3 gridGemm(NV / BN, (NB * NT) / BM);  // (4, 256)

    // 0) weights to bf16 (WqT = Wq^T)
    k_wqt<<<dim3(16, 16), dim3(32, 8)>>>(Wq, pWqT);
    k_wv<<<(NV * NV) / 1024, 256>>>(Wv, pWvR);
    // 1) CSR of token positions per batch (parallel: hist -> scan -> fill)
    k_hist<<<dim3(NCH, NB), 512>>>(idx, pCnt);
    k_scan<<<NB, 512>>>(pCnt, pOff, pOff2);
    k_fill<<<dim3(NCH, NB), 512>>>(idx, pOff2, pPos);
    // 2) L1 scatter (atomic-free via CSR), bf16 out
    k_build_l1<<<dim3(NT / 32, NB), 512>>>(pPos, pOff, pt, pA);
    // 3) K = L1 @ Wq -> KT[b][n][s] fp32
    gemm_bf16<true><<<gridGemm, 256, 40960>>>(pA, pWqT, pKT);
    // 4) S scatter grouped by q (atomic-free, single pass), bf16 out
    k_scatter_q<<<dim3(NV, NB), 512>>>(pPos, pOff, pKT, pA);
    // 5) logits = S @ Wv^T, fp32 out
    gemm_bf16<false><<<gridGemm, 256, 40960>>>(pA, pWvR, out);
}

// round 10
// speedup vs baseline: 1.7985x; 1.0273x over previous
#include <cuda_runtime.h>
#include <cuda_bf16.h>
#include <cstdint>

#define NB 16
#define NT 2048
#define NV 512
#define BM 128
#define BN 128
#define BK 32    // bf16 elements per k-tile
#define NCH 16
#define CHW (NT / NCH)  // 128

// Scratch (allocation-free rule: __device__ globals).
__device__ __nv_bfloat16 g_A[(size_t)NB * NT * NV];   // L1, then reused as S
__device__ float g_KT[(size_t)NB * NV * NT];          // K transposed per batch
__device__ __nv_bfloat16 g_WqT[NV * NV];              // Wq^T in bf16, [n][k]
__device__ __nv_bfloat16 g_WvR[NV * NV];              // Wv in bf16, [n][k]
__device__ unsigned short g_pos[NB * NT];             // CSR positions (sorted)
__device__ int g_off[NB * (NV + 1)];                  // CSR offsets
__device__ int g_cnt[NB * NCH * NV];                  // per-chunk counts
__device__ int g_off2[NB * NCH * NV];                 // per-chunk start offsets

__device__ __forceinline__ uint32_t smem_u32(const void* p) {
    return (uint32_t)__cvta_generic_to_shared(p);
}

// ---------------------------------------------------------------------------
// Wq transpose (512x512) -> bf16, [n][k] layout
// ---------------------------------------------------------------------------
__global__ void k_wqt(const float* __restrict__ W, __nv_bfloat16* __restrict__ WT) {
    __shared__ float t[32][33];
    int x = blockIdx.x * 32 + threadIdx.x;
    int y = blockIdx.y * 32 + threadIdx.y;
#pragma unroll
    for (int j = 0; j < 32; j += 8)
        t[threadIdx.y + j][threadIdx.x] = W[(size_t)(y + j) * NV + x];
    __syncthreads();
    x = blockIdx.y * 32 + threadIdx.x;
    y = blockIdx.x * 32 + threadIdx.y;
#pragma unroll
    for (int j = 0; j < 32; j += 8)
        WT[(size_t)(y + j) * NV + x] = __float2bfloat16(t[threadIdx.x][threadIdx.y + j]);
}

// ---------------------------------------------------------------------------
// Wv -> bf16 copy
// ---------------------------------------------------------------------------
__global__ void k_wv(const float* __restrict__ src, __nv_bfloat16* __restrict__ dst) {
    int i4 = (blockIdx.x * 256 + threadIdx.x) * 4;
    float4 v = *(const float4*)(src + i4);
    __nv_bfloat162* d2 = (__nv_bfloat162*)(dst + i4);
    d2[0] = __floats2bfloat162_rn(v.x, v.y);
    d2[1] = __floats2bfloat162_rn(v.z, v.w);
}

// ---------------------------------------------------------------------------
// Parallel CSR build: hist (per 128-token chunk) -> scan -> fill
// ---------------------------------------------------------------------------
__global__ void k_hist(const int* __restrict__ idx, int* __restrict__ cnt) {
    const int c = blockIdx.x, b = blockIdx.y, v = threadIdx.x;
    __shared__ int sidx[CHW];
    if (v < CHW) sidx[v] = idx[b * NT + c * CHW + v];
    __syncthreads();
    int n = 0;
#pragma unroll 8
    for (int r = 0; r < CHW; r++) n += (sidx[r] == v);
    cnt[(b * NCH + c) * NV + v] = n;
}

__global__ void k_scan(const int* __restrict__ cnt, int* __restrict__ off,
                       int* __restrict__ off2) {
    const int b = blockIdx.x, v = threadIdx.x;
    __shared__ int wsum[16];
    int c[NCH];
    int tot = 0;
#pragma unroll
    for (int j = 0; j < NCH; j++) {
        c[j] = cnt[(b * NCH + j) * NV + v];
        tot += c[j];
    }
    const int lane = v & 31, w = v >> 5;
    int incl = tot;
#pragma unroll
    for (int d = 1; d < 32; d <<= 1) {
        int x = __shfl_up_sync(0xffffffffu, incl, d);
        if (lane >= d) incl += x;
    }
    if (lane == 31) wsum[w] = incl;
    __syncthreads();
    if (w == 0) {
        int s = (lane < 16) ? wsum[lane] : 0;
#pragma unroll
        for (int d = 1; d < 16; d <<= 1) {
            int x = __shfl_up_sync(0xffffffffu, s, d);
            if (lane >= d) s += x;
        }
        if (lane < 16) wsum[lane] = s;
    }
    __syncthreads();
    int o = incl - tot + (w ? wsum[w - 1] : 0);  // exclusive prefix
    off[b * (NV + 1) + v] = o;
    if (v == NV - 1) off[b * (NV + 1) + NV] = NT;
#pragma unroll
    for (int j = 0; j < NCH; j++) {
        off2[(b * NCH + j) * NV + v] = o;
        o += c[j];
    }
}

__global__ void k_fill(const int* __restrict__ idx, const int* __restrict__ off2,
                       unsigned short* __restrict__ pos) {
    const int c = blockIdx.x, b = blockIdx.y, v = threadIdx.x;
    __shared__ int sidx[CHW];
    if (v < CHW) sidx[v] = idx[b * NT + c * CHW + v];
    __syncthreads();
    int o = off2[(b * NCH + c) * NV + v];
    for (int r = 0; r < CHW; r++)
        if (sidx[r] == v) pos[b * NT + (o++)] = (unsigned short)(c * CHW + r);
}

// ---------------------------------------------------------------------------
// L1[b,s,v] = sum_{r<=s, idx[b,r]==v} pt[s-r], atomic-free via CSR.
// ---------------------------------------------------------------------------
__global__ void __launch_bounds__(512)
k_build_l1(const unsigned short* __restrict__ pos, const int* __restrict__ off,
           const float* __restrict__ pt, __nv_bfloat16* __restrict__ L1) {
    const int s0 = blockIdx.x * 32, b = blockIdx.y;
    const int v = threadIdx.x;
    const int smax = s0 + 31;
    __shared__ float ptsh[NT];
    __shared__ unsigned short psh[NT];
    for (int d = v; d <= smax; d += 512) ptsh[d] = pt[d];
    for (int d = v; d < NT; d += 512) psh[d] = pos[b * NT + d];
    __syncthreads();
    float acc[32];
#pragma unroll
    for (int i = 0; i < 32; i++) acc[i] = 0.f;
    const int e0 = off[b * (NV + 1) + v], e1 = off[b * (NV + 1) + v + 1];
    for (int e = e0; e < e1; e++) {
        const int r = psh[e];
        if (r > smax) break;
        if (r <= s0) {
            const float* p = ptsh + (s0 - r);
#pragma unroll
            for (int i = 0; i < 32; i++) acc[i] += p[i];
        } else {
#pragma unroll
            for (int i = 0; i < 32; i++)
                if (s0 + i >= r) acc[i] += ptsh[s0 + i - r];
        }
    }
#pragma unroll
    for (int i = 0; i < 32; i++)
        L1[((size_t)(b * NT + s0 + i)) * NV + v] = __float2bfloat16(acc[i]);
}

// ---------------------------------------------------------------------------
// S-scatter grouped by query token q (atomic-free, single pass per (b,q))
// ---------------------------------------------------------------------------
__global__ void __launch_bounds__(512)
k_scatter_q(const unsigned short* __restrict__ pos, const int* __restrict__ off,
            const float* __restrict__ KT, __nv_bfloat16* __restrict__ S) {
    const int q = blockIdx.x, b = blockIdx.y;
    const int v = threadIdx.x;
    __shared__ float colsh[NT];
    __shared__ unsigned short psh[NT];
    __shared__ int tq0sh[2];

    if (v < 2) tq0sh[v] = off[b * (NV + 1) + q + v];
    __syncthreads();
    const int eq0 = tq0sh[0], eq1 = tq0sh[1];
    const int lenT = eq1 - eq0;
    if (lenT == 0) return;

    const unsigned short* pb = pos + b * NT;
    const int tlast = pb[eq1 - 1];

    {
        const float* src = KT + ((size_t)(b * NV + q)) * NT;
        for (int c4 = v; c4 * 4 <= tlast; c4 += 512) {
            uint32_t dst = smem_u32(&colsh[c4 * 4]);
            asm volatile("cp.async.cg.shared.global [%0], [%1], 16;" ::"r"(dst),
                         "l"(src + c4 * 4));
        }
        asm volatile("cp.async.commit_group;");
    }
    for (int d = v; d < NT; d += 512) psh[d] = pb[d];
    asm volatile("cp.async.wait_group 0;");
    __syncthreads();

    int e = off[b * (NV + 1) + v];
    const int e1 = off[b * (NV + 1) + v + 1];
    float acc = 0.f;
    __nv_bfloat16* Sb = S + (size_t)b * NT * NV + v;
    for (int j = 0; j < lenT; j++) {
        const int t = psh[eq0 + j];
        while (e < e1 && psh[e] <= t) { acc += colsh[psh[e]]; e++; }
        Sb[(size_t)t * NV] = __float2bfloat16(acc);
    }
}

// ---------------------------------------------------------------------------
// bf16 GEMM, CTA 128x128, BK=32 (bf16), 8 warps of 64x32 each,
// cp.async double-buffered, stride-20-u32 padded smem, ldmatrix fragment
// loads (LDSM; 12 instr per warp-chunk vs 48 scalar LDS).
// B row-major [n][k]. C[m,n] = sum_k A[m,k]*B[n,k], fp32 out.
//   TRANS_OUT=true : C[m,n] -> KT[b][n][s] via shared-staged transpose
// ---------------------------------------------------------------------------
template <bool TRANS_OUT>
__global__ void __launch_bounds__(256, 2)
gemm_bf16(const __nv_bfloat16* __restrict__ A,
          const __nv_bfloat16* __restrict__ Bsrc, float* __restrict__ C) {
    extern __shared__ __align__(16) uint32_t sm[];  // 10240 u32 = 40KB
    uint32_t* Asm = sm;          // [2][128][20] u32 (16 data + 4 pad per row)
    uint32_t* Bsm = sm + 5120;   // [2][128][20]

    const int tid = threadIdx.x;
    const int lane = tid & 31, warp = tid >> 5;
    const int wm = (warp & 1) * 64, wn = (warp >> 1) * 32;
    const int q = lane >> 2, t4 = lane & 3;
    const int m0 = blockIdx.y * BM, n0 = blockIdx.x * BN;

    // ldmatrix per-lane address offsets (u32 units, within one buffer)
    const int g = lane >> 3, lr = lane & 7;
    // A tile i, k16-step ks: row = wm + i*16 + (g&1)*8 + lr, col = ks*8 + (g>>1)*4
    const int a_base = (wm + (g & 1) * 8 + lr) * 20 + (g >> 1) * 4;
    // B tile-pair jj (tiles 2jj,2jj+1), ks: n = wn + jj*16 + (g>>1)*8 + lr,
    //                                       col = ks*8 + (g&1)*4
    const int b_base = (wn + (g >> 1) * 8 + lr) * 20 + (g & 1) * 4;

    float c[4][4][4];
#pragma unroll
    for (int i = 0; i < 4; i++)
#pragma unroll
        for (int j = 0; j < 4; j++)
#pragma unroll
            for (int r = 0; r < 4; r++) c[i][j][r] = 0.f;

#define ISSUE_TILE(KT_, BUF_)                                                  \
    do {                                                                       \
        _Pragma("unroll") for (int i_ = 0; i_ < 2; i_++) {                     \
            int f = tid + i_ * 256;                                            \
            int m_ = f >> 2, k4 = f & 3;                                       \
            const __nv_bfloat16* src =                                         \
                A + (size_t)(m0 + m_) * NV + (KT_) + k4 * 8;                   \
            uint32_t dst =                                                     \
                smem_u32(&Asm[(BUF_)*2560 + m_ * 20 + k4 * 4]);                \
            asm volatile("cp.async.cg.shared.global [%0], [%1], 16;" ::"r"(    \
                             dst),                                             \
                         "l"(src));                                            \
        }                                                                      \
        _Pragma("unroll") for (int i_ = 0; i_ < 2; i_++) {                     \
            int f = tid + i_ * 256;                                            \
            int n_ = f >> 2, k4 = f & 3;                                       \
            const __nv_bfloat16* src =                                         \
                Bsrc + (size_t)(n0 + n_) * NV + (KT_) + k4 * 8;                \
            uint32_t dst =                                                     \
                smem_u32(&Bsm[(BUF_)*2560 + n_ * 20 + k4 * 4]);                \
            asm volatile("cp.async.cg.shared.global [%0], [%1], 16;" ::"r"(    \
                             dst),                                             \
                         "l"(src));                                            \
        }                                                                      \
        asm volatile("cp.async.commit_group;");                                \
    } while (0)

    ISSUE_TILE(0, 0);
    const int NKT = NV / BK;  // 16
    for (int it = 0; it < NKT; it++) {
        const int buf = it & 1;
        if (it + 1 < NKT) {
            ISSUE_TILE((it + 1) * BK, buf ^ 1);
            asm volatile("cp.async.wait_group 1;");
        } else {
            asm volatile("cp.async.wait_group 0;");
        }
        __syncthreads();

        const uint32_t Abase = smem_u32(&Asm[buf * 2560]);
        const uint32_t Bbase = smem_u32(&Bsm[buf * 2560]);
#pragma unroll
        for (int ks = 0; ks < 2; ks++) {
            uint32_t a[4][4], bf_[4][2];
#pragma unroll
            for (int i = 0; i < 4; i++) {
                const uint32_t addr = Abase + (a_base + i * 320 + ks * 8) * 4;
                asm volatile(
                    "ldmatrix.sync.aligned.m8n8.x4.shared.b16 "
                    "{%0, %1, %2, %3}, [%4];"
                    : "=r"(a[i][0]), "=r"(a[i][1]), "=r"(a[i][2]), "=r"(a[i][3])
                    : "r"(addr));
            }
#pragma unroll
            for (int jj = 0; jj < 2; jj++) {
                const uint32_t addr = Bbase + (b_base + jj * 320 + ks * 8) * 4;
                asm volatile(
                    "ldmatrix.sync.aligned.m8n8.x4.shared.b16 "
                    "{%0, %1, %2, %3}, [%4];"
                    : "=r"(bf_[2 * jj][0]), "=r"(bf_[2 * jj][1]),
                      "=r"(bf_[2 * jj + 1][0]), "=r"(bf_[2 * jj + 1][1])
                    : "r"(addr));
            }
#pragma unroll
            for (int i = 0; i < 4; i++)
#pragma unroll
                for (int j = 0; j < 4; j++)
                    asm volatile(
                        "mma.sync.aligned.m16n8k16.row.col.f32.bf16.bf16.f32 "
                        "{%0,%1,%2,%3}, {%4,%5,%6,%7}, {%8,%9}, {%0,%1,%2,%3};"
                        : "+f"(c[i][j][0]), "+f"(c[i][j][1]),
                          "+f"(c[i][j][2]), "+f"(c[i][j][3])
                        : "r"(a[i][0]), "r"(a[i][1]), "r"(a[i][2]),
                          "r"(a[i][3]), "r"(bf_[j][0]), "r"(bf_[j][1]));
        }
        __syncthreads();
    }
#undef ISSUE_TILE

    if (TRANS_OUT) {
        // C[m,n] -> KT[b][n][s], staged through shared for coalesced stores
        const int b = m0 >> 11;  // / NT
        const int s0 = m0 & (NT - 1);
        float* stg = (float*)sm;  // [64][136] floats = 34816B < 40960B
#pragma unroll
        for (int p = 0; p < 2; p++) {
            __syncthreads();
            if ((warp >> 2) == p) {
#pragma unroll
                for (int i = 0; i < 4; i++)
#pragma unroll
                    for (int j = 0; j < 4; j++)
#pragma unroll
                        for (int r = 0; r < 4; r++) {
                            int row = wm + i * 16 + q + (r >> 1) * 8;
                            int col = wn + j * 8 + 2 * t4 + (r & 1) - p * 64;
                            stg[col * 136 + row] = c[i][j][r];
                        }
            }
            __syncthreads();
            const int nn = tid >> 2, ch = tid & 3;
            float* dst = C + ((size_t)(b * NV + n0 + p * 64 + nn)) * NT + s0;
            const float* srow = stg + nn * 136;
#pragma unroll
            for (int w = 0; w < 8; w++) {
                int f = ch * 32 + w * 4;
                *(float4*)(dst + f) = *(const float4*)(srow + f);
            }
        }
    } else {
        float* Cb = C + (size_t)m0 * NV + n0;
#pragma unroll
        for (int i = 0; i < 4; i++)
#pragma unroll
            for (int j = 0; j < 4; j++) {
                const int row = wm + i * 16 + q;
                const int col = wn + j * 8 + 2 * t4;
                float2 v0 = make_float2(c[i][j][0], c[i][j][1]);
                float2 v1 = make_float2(c[i][j][2], c[i][j][3]);
                *(float2*)&Cb[(size_t)row * NV + col] = v0;
                *(float2*)&Cb[(size_t)(row + 8) * NV + col] = v1;
            }
    }
}

// ---------------------------------------------------------------------------
extern "C" void kernel_launch(void* const* d_in, const int* in_sizes, int n_in,
                              void* d_out, int out_size) {
    const int* idx = (const int*)d_in[0];     // (B,T) int32
    const float* pt = (const float*)d_in[1];  // (T,1) f32
    const float* Wq = (const float*)d_in[2];  // (V,V) f32
    const float* Wv = (const float*)d_in[3];  // (V,V) f32
    float* out = (float*)d_out;               // (B,T,V) f32

    __nv_bfloat16 *pA = nullptr, *pWqT = nullptr, *pWvR = nullptr;
    float* pKT = nullptr;
    unsigned short* pPos = nullptr;
    int *pOff = nullptr, *pCnt = nullptr, *pOff2 = nullptr;
    cudaGetSymbolAddress((void**)&pA, g_A);
    cudaGetSymbolAddress((void**)&pKT, g_KT);
    cudaGetSymbolAddress((void**)&pWqT, g_WqT);
    cudaGetSymbolAddress((void**)&pWvR, g_WvR);
    cudaGetSymbolAddress((void**)&pPos, g_pos);
    cudaGetSymbolAddress((void**)&pOff, g_off);
    cudaGetSymbolAddress((void**)&pCnt, g_cnt);
    cudaGetSymbolAddress((void**)&pOff2, g_off2);

    cudaFuncSetAttribute(gemm_bf16<true>,
                         cudaFuncAttributeMaxDynamicSharedMemorySize, 40960);
    cudaFuncSetAttribute(gemm_bf16<false>,
                         cudaFuncAttributeMaxDynamicSharedMemorySize, 40960);

    dim3 gridGemm(NV / BN, (NB * NT) / BM);  // (4, 256)

    // 0) weights to bf16 (WqT = Wq^T)
    k_wqt<<<dim3(16, 16), dim3(32, 8)>>>(Wq, pWqT);
    k_wv<<<(NV * NV) / 1024, 256>>>(Wv, pWvR);
    // 1) CSR of token positions per batch (parallel: hist -> scan -> fill)
    k_hist<<<dim3(NCH, NB), 512>>>(idx, pCnt);
    k_scan<<<NB, 512>>>(pCnt, pOff, pOff2);
    k_fill<<<dim3(NCH, NB), 512>>>(idx, pOff2, pPos);
    // 2) L1 scatter (atomic-free via CSR), bf16 out
    k_build_l1<<<dim3(NT / 32, NB), 512>>>(pPos, pOff, pt, pA);
    // 3) K = L1 @ Wq -> KT[b][n][s] fp32
    gemm_bf16<true><<<gridGemm, 256, 40960>>>(pA, pWqT, pKT);
    // 4) S scatter grouped by q (atomic-free, single pass), bf16 out
    k_scatter_q<<<dim3(NV, NB), 512>>>(pPos, pOff, pKT, pA);
    // 5) logits = S @ Wv^T, fp32 out
    gemm_bf16<false><<<gridGemm, 256, 40960>>>(pA, pWvR, out);
}